// round 1
// baseline (speedup 1.0000x reference)
#include <cuda_runtime.h>
#include <cuda_bf16.h>
#include <math_constants.h>

// Problem constants (shapes fixed by the reference)
#define B_MAX 4096
#define NF 50
#define E 128
#define A 64
#define M 8
#define FM (NF*M)   // 400

// Scratch (no cudaMalloc allowed)
__device__ float g_ak[B_MAX * FM];   // att_key [b][f][m]
__device__ float g_mx[FM];           // max over batch per (f,m)
__device__ float g_se[FM];           // sum exp over batch per (f,m)

// ---------------------------------------------------------------------------
// Kernel 1: per (b,f): mask+normalize friend embedding, cross with uid_n,
// project through Key -> att_key[b][f][m].  One block per b, 8 warps,
// one warp per friend (strided).  Key rows live in registers (4 rows/lane).
// ---------------------------------------------------------------------------
__global__ __launch_bounds__(256) void k_attkey(
    const int* __restrict__ iu, const int* __restrict__ iuf,
    const float* __restrict__ uidW, const float* __restrict__ Key,
    float* __restrict__ akout, int user_pad)
{
    int b = blockIdx.x;
    int tid = threadIdx.x, lane = tid & 31, warp = tid >> 5;
    __shared__ float sUidN[E];
    __shared__ float sred[4];

    // Key rows lane*4 .. lane*4+3 (8 cols each) into registers
    float kr[4][8];
    {
        const float4* K4 = (const float4*)(Key + lane * 32);
        #pragma unroll
        for (int j = 0; j < 4; j++) {
            float4 p0 = K4[j * 2], p1 = K4[j * 2 + 1];
            kr[j][0] = p0.x; kr[j][1] = p0.y; kr[j][2] = p0.z; kr[j][3] = p0.w;
            kr[j][4] = p1.x; kr[j][5] = p1.y; kr[j][6] = p1.z; kr[j][7] = p1.w;
        }
    }

    // uid l2-normalize (threads 0..127 own one element)
    float uv = 0.f;
    if (tid < E) uv = uidW[(size_t)iu[b] * E + tid];
    float p = uv * uv;
    #pragma unroll
    for (int o = 16; o; o >>= 1) p += __shfl_xor_sync(0xffffffffu, p, o);
    if (lane == 0 && warp < 4) sred[warp] = p;
    __syncthreads();
    float n2 = sred[0] + sred[1] + sred[2] + sred[3];
    float inv = 1.f / fmaxf(sqrtf(n2), 1e-12f);
    if (tid < E) sUidN[tid] = uv * inv;
    __syncthreads();

    float un[4];
    #pragma unroll
    for (int j = 0; j < 4; j++) un[j] = sUidN[lane * 4 + j];

    const int* fids = iuf + b * NF;
    float* akb = akout + (size_t)b * FM;

    for (int f = warp; f < NF; f += 8) {
        int fid = fids[f];
        float fnm = (fid != user_pad) ? 1.f : 0.f;
        float4 v = *(const float4*)(uidW + (size_t)fid * E + lane * 4);
        v.x *= fnm; v.y *= fnm; v.z *= fnm; v.w *= fnm;
        float n2f = v.x * v.x + v.y * v.y + v.z * v.z + v.w * v.w;
        #pragma unroll
        for (int o = 16; o; o >>= 1) n2f += __shfl_xor_sync(0xffffffffu, n2f, o);
        float invf = 1.f / fmaxf(sqrtf(n2f), 1e-12f);
        float c0 = un[0] * v.x * invf, c1 = un[1] * v.y * invf;
        float c2 = un[2] * v.z * invf, c3 = un[3] * v.w * invf;
        float ak[8];
        #pragma unroll
        for (int m = 0; m < 8; m++)
            ak[m] = c0 * kr[0][m] + c1 * kr[1][m] + c2 * kr[2][m] + c3 * kr[3][m];
        #pragma unroll
        for (int m = 0; m < 8; m++) {
            #pragma unroll
            for (int o = 16; o; o >>= 1) ak[m] += __shfl_xor_sync(0xffffffffu, ak[m], o);
        }
        if (lane == 0) {
            *(float4*)(akb + f * 8)     = make_float4(ak[0], ak[1], ak[2], ak[3]);
            *(float4*)(akb + f * 8 + 4) = make_float4(ak[4], ak[5], ak[6], ak[7]);
        }
    }
}

// ---------------------------------------------------------------------------
// Kernel 2: batch-axis softmax stats.  One block per (f,m): max over b, then
// sum of exp(x - max).  Data is L2-resident (6.5 MB).
// ---------------------------------------------------------------------------
__global__ __launch_bounds__(256) void k_softstats(
    const float* __restrict__ ak, float* __restrict__ mx,
    float* __restrict__ se, int nb)
{
    int fm = blockIdx.x;
    int tid = threadIdx.x, lane = tid & 31, warp = tid >> 5;
    __shared__ float sred[8];

    float m = -CUDART_INF_F;
    for (int b = tid; b < nb; b += 256) m = fmaxf(m, ak[(size_t)b * FM + fm]);
    #pragma unroll
    for (int o = 16; o; o >>= 1) m = fmaxf(m, __shfl_xor_sync(0xffffffffu, m, o));
    if (lane == 0) sred[warp] = m;
    __syncthreads();
    float mm = sred[0];
    #pragma unroll
    for (int w = 1; w < 8; w++) mm = fmaxf(mm, sred[w]);
    __syncthreads();

    float s = 0.f;
    for (int b = tid; b < nb; b += 256) s += __expf(ak[(size_t)b * FM + fm] - mm);
    #pragma unroll
    for (int o = 16; o; o >>= 1) s += __shfl_xor_sync(0xffffffffu, s, o);
    if (lane == 0) sred[warp] = s;
    __syncthreads();
    if (tid == 0) {
        float st = 0.f;
        #pragma unroll
        for (int w = 0; w < 8; w++) st += sred[w];
        mx[fm] = mm;
        se[fm] = st;
    }
}

// ---------------------------------------------------------------------------
// Kernel 3: main fused pipeline per b.  128 threads; thread owns element
// e = tid of every [E]-vector.  WA column (64 values) held in registers
// per thread (a = tid&63, e-half = tid>>6) to keep h = f2@WA FFMA-bound.
// ---------------------------------------------------------------------------
__global__ __launch_bounds__(128) void k_main(
    const int* __restrict__ iu, const int* __restrict__ ii,
    const int* __restrict__ iuf, const float* __restrict__ uidW,
    const float* __restrict__ iidW, const float* __restrict__ ibias,
    const float* __restrict__ Memw, const float* __restrict__ WA,
    const float* __restrict__ BA, const float* __restrict__ Uo,
    const float* __restrict__ ak, const float* __restrict__ mx,
    const float* __restrict__ se, float* __restrict__ out, int user_pad)
{
    int b = blockIdx.x, tid = threadIdx.x, lane = tid & 31, warp = tid >> 5;
    int a = tid & 63, half = tid >> 6;

    __shared__ float sMem[M * E];     // [m][e]
    __shared__ float sAm[FM];         // att_mem (masked, normalized)
    __shared__ float4 sF2[E / 4];
    __shared__ float sH[128];
    __shared__ float sred[4];
    __shared__ float sBA[A], sUo[A];

    for (int i = tid; i < M * E; i += 128) sMem[i] = Memw[i];
    if (tid < A) { sBA[tid] = BA[tid]; sUo[tid] = Uo[tid]; }

    const int* fids = iuf + b * NF;
    const float* akb = ak + (size_t)b * FM;

    // precompute att_mem[f][m] = fn * exp(ak - mx) / se for whole block
    for (int i = tid; i < FM; i += 128) {
        int f = i >> 3;
        float fnm = (fids[f] != user_pad) ? 1.f : 0.f;
        sAm[i] = fnm * __expf(akb[i] - mx[i]) / se[i];
    }

    // WA column for (half, a) into registers: WA[(half*64+e0)*64 + a]
    float wreg[64];
    #pragma unroll
    for (int e0 = 0; e0 < 64; e0++) wreg[e0] = WA[(half * 64 + e0) * A + a];
    __syncthreads();

    float uidv = uidW[(size_t)iu[b] * E + tid];
    float facc = 0.f, jsum = 0.f;

    for (int f = 0; f < NF; f++) {
        int fid = fids[f];
        float fnm = (fid != user_pad) ? 1.f : 0.f;
        float fe = uidW[(size_t)fid * E + tid] * fnm;

        float f1 = 0.f;
        #pragma unroll
        for (int m = 0; m < M; m++) f1 += sAm[f * 8 + m] * sMem[m * E + tid];
        float f2 = f1 * fe;
        ((float*)sF2)[tid] = f2;
        __syncthreads();

        // h partial: this thread's 64-element half of the dot for column a
        float hp = 0.f;
        const float4* F4 = sF2 + half * 16;
        #pragma unroll
        for (int e4 = 0; e4 < 16; e4++) {
            float4 q = F4[e4];
            hp += q.x * wreg[e4 * 4] + q.y * wreg[e4 * 4 + 1]
                + q.z * wreg[e4 * 4 + 2] + q.w * wreg[e4 * 4 + 3];
        }
        sH[tid] = hp;
        __syncthreads();

        if (tid < 64) {
            float hv = fmaxf(sH[tid] + sH[tid + 64] + sBA[tid], 0.f);
            float jp = hv * sUo[tid];
            #pragma unroll
            for (int o = 16; o; o >>= 1) jp += __shfl_xor_sync(0xffffffffu, jp, o);
            if (lane == 0) sred[warp] = jp;
        }
        __syncthreads();

        float j = fnm * __expf(sred[0] + sred[1]);
        jsum += j;
        facc += j * f2;
        __syncthreads();   // protect sF2 / sred for next iteration
    }

    float user = uidv + facc / (jsum + 1e-8f);
    int it = ii[b];
    float iv = iidW[(size_t)it * E + tid];
    float pp = user * iv;
    #pragma unroll
    for (int o = 16; o; o >>= 1) pp += __shfl_xor_sync(0xffffffffu, pp, o);
    if (lane == 0) sred[warp] = pp;
    __syncthreads();
    if (tid == 0) out[b] = sred[0] + sred[1] + sred[2] + sred[3] + ibias[it];
}

// ---------------------------------------------------------------------------
extern "C" void kernel_launch(void* const* d_in, const int* in_sizes, int n_in,
                              void* d_out, int out_size)
{
    const int*   input_u  = (const int*)d_in[0];
    const int*   input_i  = (const int*)d_in[1];
    const int*   input_uf = (const int*)d_in[2];
    const float* uidW     = (const float*)d_in[3];
    const float* iidW     = (const float*)d_in[4];
    const float* i_bias   = (const float*)d_in[5];
    const float* Key      = (const float*)d_in[6];
    const float* Memw     = (const float*)d_in[7];
    const float* WA       = (const float*)d_in[8];
    const float* BA       = (const float*)d_in[9];
    const float* Uo       = (const float*)d_in[10];
    float* out = (float*)d_out;

    int nb = in_sizes[0];                 // 4096
    int user_pad = in_sizes[3] / E - 1;   // padding user id

    float *g_ak_p, *g_mx_p, *g_se_p;
    // __device__ globals: take addresses via unified symbols (works in device code
    // directly; on host we use cudaGetSymbolAddress-free approach via kernels
    // referencing the globals themselves). We only need them as kernel args:
    // use cudaGetSymbolAddress (allowed: no allocation).
    cudaGetSymbolAddress((void**)&g_ak_p, g_ak);
    cudaGetSymbolAddress((void**)&g_mx_p, g_mx);
    cudaGetSymbolAddress((void**)&g_se_p, g_se);

    k_attkey<<<nb, 256>>>(input_u, input_uf, uidW, Key, g_ak_p, user_pad);
    k_softstats<<<FM, 256>>>(g_ak_p, g_mx_p, g_se_p, nb);
    k_main<<<nb, 128>>>(input_u, input_i, input_uf, uidW, iidW, i_bias,
                        Memw, WA, BA, Uo, g_ak_p, g_mx_p, g_se_p, out, user_pad);
}